// round 4
// baseline (speedup 1.0000x reference)
#include <cuda_runtime.h>
#include <cstdint>

#define NPAT  8192
#define NBITS 4096
#define WPC   256            // 32-bit words per column = 8192/32
#define NCTA  8              // cluster size
#define NTHR  128
#define RPT   8              // rows per thread = 8192/(NCTA*NTHR)
#define NBUF  4              // round buffers (skew bound proof needs 4)

// Scratch (allocation-free rule: __device__ globals)
__device__ unsigned g_Wb[NBITS * WPC];   // 4 MB packed bits, [col][word]
__device__ float    g_h0[NPAT];          // initial h = W @ state (exact ints)

// ---------------------------------------------------------------------------
// Pack W (+-1 floats) into bits. bit=1 <=> W>0. Word (col,g) holds rows 32g..32g+31.
__global__ void pack_kernel(const float* __restrict__ W) {
    int tid = blockIdx.x * blockDim.x + threadIdx.x;
    int col = tid & (NBITS - 1);
    int g   = tid >> 12;
    unsigned bits = 0;
    const float* base = W + (long)(g * 32) * NBITS + col;
#pragma unroll
    for (int j = 0; j < 32; j++) {
        float w = base[(long)j * NBITS];
        bits |= (w > 0.0f ? 1u : 0u) << j;
    }
    g_Wb[col * WPC + g] = bits;
}

// h0[r] = W[r,:] . state  (exact, |h|<=4096). One warp per row.
__global__ void h0_kernel(const float* __restrict__ W, const float* __restrict__ s) {
    int warp = (blockIdx.x * blockDim.x + threadIdx.x) >> 5;
    int lane = threadIdx.x & 31;
    const float* row = W + (long)warp * NBITS;
    float acc = 0.0f;
#pragma unroll 4
    for (int c = lane; c < NBITS; c += 32)
        acc = fmaf(row[c], s[c], acc);
#pragma unroll
    for (int off = 16; off; off >>= 1)
        acc += __shfl_xor_sync(0xffffffffu, acc, off);
    if (lane == 0) g_h0[warp] = acc;
}

// ---------------------------------------------------------------------------
// PTX helpers
static __device__ __forceinline__ unsigned smem_u32(const void* p) {
    return (unsigned)__cvta_generic_to_shared(p);
}
static __device__ __forceinline__ unsigned mapa_rank(unsigned addr, unsigned rank) {
    unsigned r;
    asm("mapa.shared::cluster.u32 %0, %1, %2;" : "=r"(r) : "r"(addr), "r"(rank));
    return r;
}
static __device__ __forceinline__ void st_remote(unsigned addr, int v) {
    asm volatile("st.shared::cluster.u32 [%0], %1;" :: "r"(addr), "r"(v) : "memory");
}
static __device__ __forceinline__ void arrive_remote(unsigned addr) {
    asm volatile("mbarrier.arrive.release.cluster.shared::cluster.b64 _, [%0];"
                 :: "r"(addr) : "memory");
}
static __device__ __forceinline__ void mbar_init(unsigned addr, unsigned cnt) {
    asm volatile("mbarrier.init.shared.b64 [%0], %1;" :: "r"(addr), "r"(cnt) : "memory");
}
static __device__ __forceinline__ void mbar_wait(unsigned addr, unsigned parity) {
    asm volatile(
        "{\n\t.reg .pred P;\n"
        "WL%=:\n\t"
        "mbarrier.try_wait.parity.acquire.cluster.shared::cta.b64 P, [%0], %1, 0x989680;\n\t"
        "@P bra WD%=;\n\t"
        "bra WL%=;\n"
        "WD%=:\n\t}"
        :: "r"(addr), "r"(parity) : "memory");
}
static __device__ __forceinline__ unsigned ctarank() {
    unsigned r; asm("mov.u32 %0, %%cluster_ctarank;" : "=r"(r)); return r;
}
static __device__ __forceinline__ void cluster_sync() {
    asm volatile("barrier.cluster.arrive.aligned;" ::: "memory");
    asm volatile("barrier.cluster.wait.aligned;" ::: "memory");
}

// ---------------------------------------------------------------------------
// Greedy sweep across an 8-CTA cluster, EAGER both-branch exchange:
//  - Round r (r>=1) carries, per CTA, BOTH candidate-energy partials for step
//    r-1: PA (if step r-2 accepted) and PR (if rejected). Sent right after the
//    local reduction (bar A), NOT gated by any decision.
//  - Receiver sums both columns over the 8 CTAs and selects with its own
//    previous decision -> decision latency chain spans 2 steps instead of 1.
//  - 4 round buffers: first reuse of round r's buffer is round r+4, whose send
//    is gated (writer barB -> wake(r+2) -> all arrives(r+2), each issued after
//    that CTA completed iter r-1 incl. its read of round r). Write-after-read
//    safe. mbar[r&3], parity (r>>2)&1.
//  - int32-exact; matches the fp32 reference decisions exactly.
__global__ void __launch_bounds__(NTHR, 1) __cluster_dims__(NCTA, 1, 1)
hop_kernel(const float* __restrict__ state,
           const int*   __restrict__ perm,
           float*       __restrict__ out)
{
    __shared__ int           s_perm[NBITS];
    __shared__ int8_t        s_vi[NBITS];
    __shared__ unsigned char s_acc[NBITS];
    __shared__ int           s_part[NBUF][NCTA][2];  // [buf][writer cta][PA,PR]
    __shared__ int           s_spec[2][4][2];        // [k&1][warp][PA,PR] staging
    __shared__ int           s_dec;
    __shared__ __align__(8) unsigned long long s_mbar[NBUF];

    const int tid  = threadIdx.x;
    const int lane = tid & 31;
    const int wid  = tid >> 5;
    const unsigned rank = ctarank();

    if (tid == 0) {
#pragma unroll
        for (int b = 0; b < NBUF; b++)
            mbar_init(smem_u32(&s_mbar[b]), NCTA);
    }

    for (int k = tid; k < NBITS; k += NTHR) {
        int i = perm[k];
        s_perm[k] = i;
        s_vi[k]   = (state[i] > 0.0f) ? (int8_t)1 : (int8_t)-1;
    }

    int h[RPT];
    const int rowBase = (int)rank * (NCTA * NTHR) + tid * RPT;
#pragma unroll
    for (int j = 0; j < RPT; j++)
        h[j] = (int)g_h0[rowBase + j];

    __syncthreads();
    cluster_sync();    // mbarriers initialized cluster-wide

    // Remote base addresses (lane L of warp 0 targets CTA L). Offsets into the
    // remote CTA's smem window are plain address arithmetic on the mapa result.
    unsigned rem_part = 0, rem_mbar = 0;
    if (wid == 0 && lane < NCTA) {
        rem_part = mapa_rank(smem_u32(&s_part[0][rank][0]), lane);
        rem_mbar = mapa_rank(smem_u32(&s_mbar[0]), lane);
    }

    const int wordOff = (int)rank * 32 + (tid >> 2);  // word within column
    const int bsh     = (tid & 3) * 8;                // this thread's byte

    // ---- round 0: initial partial S (both slots identical) ----
    {
        int a = 0;
#pragma unroll
        for (int j = 0; j < RPT; j++) { int m = max(h[j], 0); a += m * m; }
        int ws = __reduce_add_sync(0xffffffffu, a);
        if (lane == 0) s_spec[0][wid][0] = ws;
        __syncthreads();
        if (wid == 0 && lane < NCTA) {
            int P = s_spec[0][0][0] + s_spec[0][1][0] + s_spec[0][2][0] + s_spec[0][3][0];
            st_remote(rem_part + 0, P);            // buf 0, our rank, slot PA
            st_remote(rem_part + 4, P);            // slot PR
            arrive_remote(rem_mbar + 0);
        }
    }

    // ---- round 1: candidate step 0 (single branch; duplicate into both) ----
    int hc[RPT];
    {
        unsigned w0 = g_Wb[s_perm[0] * WPC + wordOff];
        int v = s_vi[0], p2 = 2 * v, m4 = -4 * v;
        unsigned bb = w0 >> bsh;
        int a = 0;
#pragma unroll
        for (int j = 0; j < RPT; j++) {
            int b = (int)((bb >> j) & 1u);
            hc[j] = h[j] + p2 + b * m4;
            int m = max(hc[j], 0); a += m * m;
        }
        int ws = __reduce_add_sync(0xffffffffu, a);
        if (lane == 0) s_spec[1][wid][0] = ws;
        __syncthreads();
        if (wid == 0 && lane < NCTA) {
            int P = s_spec[1][0][0] + s_spec[1][1][0] + s_spec[1][2][0] + s_spec[1][3][0];
            unsigned dst = rem_part + 1u * (NCTA * 2u * 4u);   // buf 1
            st_remote(dst + 0, P);
            st_remote(dst + 4, P);
            arrive_remote(rem_mbar + 8);
        }
    }

    // warp0 consumes round 0 -> S_prev.
    int S_prev = 0, aprev = 0;                // aprev: decision of step k-1
    if (wid == 0) {
        mbar_wait(smem_u32(&s_mbar[0]), 0);
#pragma unroll
        for (int c = 0; c < NCTA; c++) S_prev += s_part[0][c][0];
    }

    unsigned wspec = g_Wb[s_perm[1] * WPC + wordOff];  // column for k=0 spec

    for (int k = 0; k < NBITS; k++) {
        // Prefetch next speculation column (L2-resident).
        int pn = (k + 2 < NBITS) ? s_perm[k + 2] : s_perm[NBITS - 1];
        unsigned wnext = g_Wb[pn * WPC + wordOff];

        // Both-branch speculation for step k+1 (outcomes of step k).
        int sidx = (k + 1 < NBITS) ? (k + 1) : (NBITS - 1);
        int v = s_vi[sidx], p2 = 2 * v, m4 = -4 * v;
        unsigned bb = wspec >> bsh;
        int hA[RPT], hR[RPT];
        int aA = 0, aR = 0;
#pragma unroll
        for (int j = 0; j < RPT; j++) {
            int b = (int)((bb >> j) & 1u);
            int d = p2 + b * m4;
            hA[j] = hc[j] + d;
            hR[j] = h[j]  + d;
            int mA = max(hA[j], 0); aA += mA * mA;
            int mR = max(hR[j], 0); aR += mR * mR;
        }
        int wsA = __reduce_add_sync(0xffffffffu, aA);
        int wsR = __reduce_add_sync(0xffffffffu, aR);
        const int sb = k & 1;
        if (lane == 0) { s_spec[sb][wid][0] = wsA; s_spec[sb][wid][1] = wsR; }
        __syncthreads();                               // bar A

        int accept;
        if (wid == 0) {
            // EAGER send of round k+2 (payload for step k+1) — not decision-gated.
            if (k < NBITS - 1 && lane < NCTA) {
                int PA = s_spec[sb][0][0] + s_spec[sb][1][0] + s_spec[sb][2][0] + s_spec[sb][3][0];
                int PR = s_spec[sb][0][1] + s_spec[sb][1][1] + s_spec[sb][2][1] + s_spec[sb][3][1];
                unsigned sbuf = (unsigned)((k + 2) & (NBUF - 1));
                unsigned dst  = rem_part + sbuf * (NCTA * 2u * 4u);
                st_remote(dst + 0, PA);
                st_remote(dst + 4, PR);
                arrive_remote(rem_mbar + sbuf * 8u);
            }

            // Wait round r = k+1 (both-branch payload for step k), select, decide.
            const int r  = k + 1;
            const int rb = r & (NBUF - 1);
            mbar_wait(smem_u32(&s_mbar[rb]), (unsigned)((r >> 2) & 1));
            int pa = (lane < NCTA) ? s_part[rb][lane][0] : 0;
            int pr = (lane < NCTA) ? s_part[rb][lane][1] : 0;
            int SA = __reduce_add_sync(0xffffffffu, pa);
            int SR = __reduce_add_sync(0xffffffffu, pr);
            int S_new = aprev ? SA : SR;
            accept = (S_new > S_prev);                 // e_new < e_prev
            if (accept) S_prev = S_new;
            aprev = accept;
            if (lane == 0) {
                s_dec = accept;
                if (rank == 0) s_acc[k] = (unsigned char)accept;
            }
        }
        __syncthreads();                               // bar B: decision visible
        accept = s_dec;

        // Commit (off the cross-CTA critical path).
        if (accept) {
#pragma unroll
            for (int j = 0; j < RPT; j++) h[j] = hc[j];
#pragma unroll
            for (int j = 0; j < RPT; j++) hc[j] = hA[j];
        } else {
#pragma unroll
            for (int j = 0; j < RPT; j++) hc[j] = hR[j];
        }
        wspec = wnext;
    }

    if (rank == 0) {
        __syncthreads();
        for (int k = tid; k < NBITS; k += NTHR) {
            int i = s_perm[k];
            int vv = (int)s_vi[k];
            out[i] = (float)(s_acc[k] ? -vv : vv);
        }
    }
}

// ---------------------------------------------------------------------------
extern "C" void kernel_launch(void* const* d_in, const int* in_sizes, int n_in,
                              void* d_out, int out_size)
{
    const float* W     = (const float*)d_in[0];   // [8192, 4096]
    const float* state = (const float*)d_in[1];   // [4096]
    const int*   perm  = (const int*)  d_in[2];   // [4096]
    float*       out   = (float*)d_out;           // [4096]

    pack_kernel<<<(NBITS * WPC) / 256, 256>>>(W);
    h0_kernel<<<NPAT / 8, 256>>>(W, state);
    hop_kernel<<<NCTA, NTHR>>>(state, perm, out);
}

// round 14
// speedup vs baseline: 2.2272x; 2.2272x over previous
#include <cuda_runtime.h>
#include <cstdint>

#define NPAT  8192
#define NBITS 4096
#define WPC   256            // 32-bit words per column = 8192/32
#define NTHR  512
#define RPT   16             // rows per thread = 8192/512

// Scratch (allocation-free rule: __device__ globals)
__device__ unsigned g_Wb[NBITS * WPC];   // 4 MB packed bits, [col][word]
__device__ float    g_h0[NPAT];          // initial h = W @ state (exact ints)

// ---------------------------------------------------------------------------
// Pack W (+-1 floats) into bits. bit=1 <=> W>0. Word (col,g) holds rows 32g..32g+31.
__global__ void pack_kernel(const float* __restrict__ W) {
    int tid = blockIdx.x * blockDim.x + threadIdx.x;
    int col = tid & (NBITS - 1);
    int g   = tid >> 12;
    unsigned bits = 0;
    const float* base = W + (long)(g * 32) * NBITS + col;
#pragma unroll
    for (int j = 0; j < 32; j++) {
        float w = base[(long)j * NBITS];
        bits |= (w > 0.0f ? 1u : 0u) << j;
    }
    g_Wb[col * WPC + g] = bits;
}

// h0[r] = W[r,:] . state  (exact, |h|<=4096). One warp per row.
__global__ void h0_kernel(const float* __restrict__ W, const float* __restrict__ s) {
    int warp = (blockIdx.x * blockDim.x + threadIdx.x) >> 5;
    int lane = threadIdx.x & 31;
    const float* row = W + (long)warp * NBITS;
    float acc = 0.0f;
#pragma unroll 4
    for (int c = lane; c < NBITS; c += 32)
        acc = fmaf(row[c], s[c], acc);
#pragma unroll
    for (int off = 16; off; off >>= 1)
        acc += __shfl_xor_sync(0xffffffffu, acc, off);
    if (lane == 0) g_h0[warp] = acc;
}

// ---------------------------------------------------------------------------
// Single-CTA sequential greedy sweep, ONE __syncthreads per step.
//  - 512 threads; thread t owns rows 16t..16t+15, whose bits are the (t&1)
//    half of word g_Wb[col*WPC + (t>>1)].
//  - Per step: candidate h' = h - 2*v*W[:,col]; partial S' = sum relu(h')^2
//    (int32-exact, ~5.5 ops/row: pairwise bit extraction, 2 accumulators);
//    warp REDUX -> smem; one barrier; EVERY warp redundantly sums the 16
//    partials and decides (identical result) -> no 2nd barrier, no broadcast.
//  - s_pv[k] = (perm[k]*WPC, vi) fetched as one LDS.64 per step; s_col keeps
//    the raw column index for the epilogue.
//  - s_red double-buffered: buffer k&1 rewritten at step k+2, whose STS
//    follows bar(k+1), which each warp passes only after its step-k read.
//  - int32 decisions match the fp32 reference exactly (all sums are multiples
//    of 4 below 2^26; S_max ~3.4e7 < 2^26 — validated on HW in R4, rel_err=0).
__global__ void __launch_bounds__(NTHR, 1)
hop_kernel(const float* __restrict__ state,
           const int*   __restrict__ perm,
           float*       __restrict__ out)
{
    __shared__ int2          s_pv[NBITS];    // (col*WPC, vi)
    __shared__ short         s_col[NBITS];   // col index (epilogue only)
    __shared__ unsigned char s_acc[NBITS];
    __shared__ int           s_red[2][16];   // [step&1][warp]

    const int tid  = threadIdx.x;
    const int lane = tid & 31;
    const int wid  = tid >> 5;
    const int wordOff = tid >> 1;            // word index within a column
    const int sh      = (tid & 1) << 4;      // 0 or 16: this thread's 16 bits

    for (int k = tid; k < NBITS; k += NTHR) {
        int i = perm[k];
        s_pv[k]  = make_int2(i * WPC, (state[i] > 0.0f) ? 1 : -1);
        s_col[k] = (short)i;
    }

    int h[RPT];
#pragma unroll
    for (int j = 0; j < RPT; j++)
        h[j] = (int)g_h0[tid * RPT + j];

    __syncthreads();

    // ---- initial S, computed identically by every warp ----
    int S_prev;
    {
        int a0 = 0, a1 = 0;
#pragma unroll
        for (int j = 0; j < RPT; j += 2) {
            int m0 = max(h[j], 0);     a0 += m0 * m0;
            int m1 = max(h[j + 1], 0); a1 += m1 * m1;
        }
        int ws = __reduce_add_sync(0xffffffffu, a0 + a1);
        if (lane == 0) s_red[1][wid] = ws;
        __syncthreads();
        int x = (lane < 16) ? s_red[1][lane] : 0;
        S_prev = __reduce_add_sync(0xffffffffu, x);
        // First rewrite of s_red[1] is step k=1 (STS after bar(k=0)); this
        // read precedes our bar(k=0) arrival -> safe without an extra bar.
    }

    int2 pv = s_pv[0];
    unsigned bb = g_Wb[pv.x + wordOff];
    int      v  = pv.y;

    for (int k = 0; k < NBITS; k++) {
        const int p2 = 2 * v;        // addend when bit=0 (w = -1): +2v
        const int m4 = -4 * v;       // extra when bit=1 (w = +1): total -2v
        const int m2 = -2 * v;       // m4/2, pairs with (r & 2)
        const unsigned bw = bb >> sh;

        // Candidate h' and partial S' (11 ops per row-pair, int-exact).
        int t[RPT];
        int a0 = 0, a1 = 0;
#pragma unroll
        for (int j = 0; j < RPT; j += 2) {
            unsigned r = bw >> j;                     // bit j at 0, j+1 at 1
            int t0 = (h[j]     + p2) + (int)(r & 1u) * m4;
            int t1 = (h[j + 1] + p2) + (int)(r & 2u) * m2;
            t[j] = t0; t[j + 1] = t1;
            int m0 = max(t0, 0);
            int m1 = max(t1, 0);
            a0 += m0 * m0;
            a1 += m1 * m1;
        }

        // Prefetch next column (L2-resident; hidden under this step).
        int kn = (k + 1 < NBITS) ? (k + 1) : (NBITS - 1);
        int2 pvn = s_pv[kn];
        unsigned bbn = g_Wb[pvn.x + wordOff];

        const int buf = k & 1;
        int ws = __reduce_add_sync(0xffffffffu, a0 + a1);
        if (lane == 0) s_red[buf][wid] = ws;
        __syncthreads();                     // the ONLY barrier this step

        // Redundant decide in every warp (identical data -> identical result).
        int x = (lane < 16) ? s_red[buf][lane] : 0;
        int S_new = __reduce_add_sync(0xffffffffu, x);
        int accept = (S_new > S_prev);       // e_new < e_prev -> accept
        if (tid == 0) s_acc[k] = (unsigned char)accept;
        if (accept) {
            S_prev = S_new;
#pragma unroll
            for (int j = 0; j < RPT; j++) h[j] = t[j];
        }

        bb = bbn;
        v  = pvn.y;
    }

    __syncthreads();
    for (int k = tid; k < NBITS; k += NTHR) {
        int vv = s_pv[k].y;
        out[s_col[k]] = (float)(s_acc[k] ? -vv : vv);
    }
}

// ---------------------------------------------------------------------------
extern "C" void kernel_launch(void* const* d_in, const int* in_sizes, int n_in,
                              void* d_out, int out_size)
{
    const float* W     = (const float*)d_in[0];   // [8192, 4096]
    const float* state = (const float*)d_in[1];   // [4096]
    const int*   perm  = (const int*)  d_in[2];   // [4096]
    float*       out   = (float*)d_out;           // [4096]

    pack_kernel<<<(NBITS * WPC) / 256, 256>>>(W);
    h0_kernel<<<NPAT / 8, 256>>>(W, state);
    hop_kernel<<<1, NTHR>>>(state, perm, out);
}